// round 9
// baseline (speedup 1.0000x reference)
#include <cuda_runtime.h>
#include <cuda_bf16.h>
#include <cstdint>

#define B_  4
#define H_  16
#define T_  2048
#define DK_ 64
#define DM_ 1024
#define M_  (B_*T_)     // 8192

// ---------------- scratch (device globals; no allocations allowed) ----------
__device__ __nv_bfloat16 g_xhi[M_*DM_];
__device__ __nv_bfloat16 g_xlo[M_*DM_];
__device__ __nv_bfloat16 g_whi[4*DM_*DM_];   // Wq | Wk | Wv | Wo (contiguous)
__device__ __nv_bfloat16 g_wlo[4*DM_*DM_];
__device__ __nv_bfloat16 g_qhi[M_*DM_];   // [b,h,t,d]
__device__ __nv_bfloat16 g_qlo[M_*DM_];
__device__ __nv_bfloat16 g_khi[M_*DM_];   // [b,h,t,d]
__device__ __nv_bfloat16 g_klo[M_*DM_];
__device__ __nv_bfloat16 g_vhi[M_*DM_];   // [b,h,d,t]  (transposed!)
__device__ __nv_bfloat16 g_vlo[M_*DM_];
__device__ __nv_bfloat16 g_ahi[M_*DM_];   // [b,t, h*64+d]
__device__ __nv_bfloat16 g_alo[M_*DM_];

// ---------------- portable PTX helpers (family-safe) -------------------------
__device__ __forceinline__ uint32_t smem_u32(const void* p) {
    uint32_t a;
    asm("{ .reg .u64 t; cvta.to.shared.u64 t, %1; cvt.u32.u64 %0, t; }" : "=r"(a) : "l"(p));
    return a;
}
__device__ __forceinline__ void cp_async16(uint32_t saddr, const void* gaddr) {
    asm volatile("cp.async.cg.shared.global [%0], [%1], 16;" :: "r"(saddr), "l"(gaddr));
}
#define CP_COMMIT() asm volatile("cp.async.commit_group;" ::: "memory")
#define CP_WAIT(n)  asm volatile("cp.async.wait_group %0;" :: "n"(n) : "memory")

__device__ __forceinline__ void ldsm_x4(uint32_t addr, uint32_t& r0, uint32_t& r1,
                                        uint32_t& r2, uint32_t& r3) {
    asm volatile("ldmatrix.sync.aligned.m8n8.x4.shared.b16 {%0,%1,%2,%3}, [%4];"
                 : "=r"(r0), "=r"(r1), "=r"(r2), "=r"(r3) : "r"(addr));
}
__device__ __forceinline__ void mma_bf16(float* c, const uint32_t* a, const uint32_t* b) {
    asm volatile(
        "mma.sync.aligned.m16n8k16.row.col.f32.bf16.bf16.f32 "
        "{%0,%1,%2,%3}, {%4,%5,%6,%7}, {%8,%9}, {%0,%1,%2,%3};"
        : "+f"(c[0]), "+f"(c[1]), "+f"(c[2]), "+f"(c[3])
        : "r"(a[0]), "r"(a[1]), "r"(a[2]), "r"(a[3]), "r"(b[0]), "r"(b[1]));
}

// pack two floats into hi/lo bf16x2 (element 0 in low 16 bits)
__device__ __forceinline__ void split2(float x0, float x1, uint32_t& hi, uint32_t& lo) {
    __nv_bfloat16 h0 = __float2bfloat16(x0), h1 = __float2bfloat16(x1);
    uint32_t u0 = *(uint16_t*)&h0, u1 = *(uint16_t*)&h1;
    hi = u0 | (u1 << 16);
    float r0 = x0 - __bfloat162float(h0), r1 = x1 - __bfloat162float(h1);
    __nv_bfloat16 g0 = __float2bfloat16(r0), g1 = __float2bfloat16(r1);
    uint32_t v0 = *(uint16_t*)&g0, v1 = *(uint16_t*)&g1;
    lo = v0 | (v1 << 16);
}

// ---------------- fp32 -> bf16 hi/lo split -----------------------------------
__global__ __launch_bounds__(256) void split_bf16_kernel(
    const float* __restrict__ x, __nv_bfloat16* __restrict__ hi,
    __nv_bfloat16* __restrict__ lo, int n4)
{
    int i = blockIdx.x * blockDim.x + threadIdx.x;
    if (i >= n4) return;
    float4 v = ((const float4*)x)[i];
    float f[4] = {v.x, v.y, v.z, v.w};
    union { __nv_bfloat16 b[4]; uint2 u; } Hh, Ll;
    #pragma unroll
    for (int k = 0; k < 4; k++) {
        Hh.b[k] = __float2bfloat16(f[k]);
        Ll.b[k] = __float2bfloat16(f[k] - __bfloat162float(Hh.b[k]));
    }
    ((uint2*)hi)[i] = Hh.u;
    ((uint2*)lo)[i] = Ll.u;
}

// ---------------- mma.sync split-bf16 GEMM -----------------------------------
// CTA 64(m) x 128(n), 128 threads = 4 warps as 2(m) x 2(n); warp tile 32x64.
// BK=16, 3-stage cp.async pipeline, 4 CTAs/SM (independent barrier domains so
// LDSM/crossbar time of one CTA hides under HMMA time of the others).
// mode 0: fused QKV epilogue (N=3072, n>>10 selects Q/K/V); mode 1: fp32 out.
#define GP2 24                              // smem pitch (bf16): 48B rows
#define GA_BYTES (64 * GP2 * 2)             // 3072 B per 64x16 A tile
#define GB_BYTES (128 * GP2 * 2)            // 6144 B per 128x16 B tile
#define G_STAGE (2 * GA_BYTES + 2 * GB_BYTES)   // 18432 B
#define G_NSTAGE 3
#define G_SMEM (G_NSTAGE * G_STAGE)         // 55296 B -> 4 CTAs/SM

__device__ __forceinline__ void gemm_issue_stage(uint32_t base,
    const __nv_bfloat16* __restrict__ Ahi, const __nv_bfloat16* __restrict__ Alo,
    const __nv_bfloat16* __restrict__ Whi, const __nv_bfloat16* __restrict__ Wlo,
    int m0, int n0, int k0, int tid)
{
    // A: 64 rows x 32B (2 chunks/row); thread -> (row=tid>>1, chunk=tid&1)
    {
        const int r = tid >> 1, c = tid & 1;
        const size_t go = (size_t)(m0 + r) * 1024 + k0 + c * 8;
        const uint32_t so = r * (GP2 * 2) + c * 16;
        cp_async16(base + so,            Ahi + go);
        cp_async16(base + GA_BYTES + so, Alo + go);
    }
    // B: 128 rows x 32B; thread -> row tid, both chunks
    {
        const size_t go = (size_t)(n0 + tid) * 1024 + k0;
        const uint32_t so = tid * (GP2 * 2);
        const uint32_t bb = base + 2 * GA_BYTES;
        cp_async16(bb + so,                 Whi + go);
        cp_async16(bb + so + 16,            Whi + go + 8);
        cp_async16(bb + GB_BYTES + so,      Wlo + go);
        cp_async16(bb + GB_BYTES + so + 16, Wlo + go + 8);
    }
}

__global__ __launch_bounds__(128, 4) void gemm_tc_kernel(
    const __nv_bfloat16* __restrict__ Ahi, const __nv_bfloat16* __restrict__ Alo,
    const __nv_bfloat16* __restrict__ Whi, const __nv_bfloat16* __restrict__ Wlo,
    const float* __restrict__ bias0, const float* __restrict__ bias1,
    const float* __restrict__ bias2,
    __nv_bfloat16* __restrict__ Qhi, __nv_bfloat16* __restrict__ Qlo,
    __nv_bfloat16* __restrict__ Khi, __nv_bfloat16* __restrict__ Klo,
    __nv_bfloat16* __restrict__ Vhi, __nv_bfloat16* __restrict__ Vlo,
    float* __restrict__ Cf, int mode)
{
    extern __shared__ char smem[];
    const uint32_t sb = smem_u32(smem);
    const int tid = threadIdx.x;
    const int wid = tid >> 5, lane = tid & 31;
    const int m0 = blockIdx.y * 64, n0 = blockIdx.x * 128;
    const int wm = (wid & 1) * 32;        // warp m-offset
    const int wn = (wid >> 1) * 64;       // warp n-offset
    const int rl = lane & 7, q = lane >> 3;

    float acc[2][8][4];
    #pragma unroll
    for (int mt = 0; mt < 2; mt++)
        #pragma unroll
        for (int nt = 0; nt < 8; nt++)
            #pragma unroll
            for (int e = 0; e < 4; e++) acc[mt][nt][e] = 0.f;

    // prologue: stages 0,1 in flight
    #pragma unroll
    for (int p = 0; p < 2; p++) {
        gemm_issue_stage(sb + p * G_STAGE, Ahi, Alo, Whi, Wlo, m0, n0, p * 16, tid);
        CP_COMMIT();
    }

    const uint32_t a_row = rl + (q & 1) * 8;
    const uint32_t a_cofs = (q >> 1) * 8;
    const uint32_t b_row = rl + (q >> 1) * 8;
    const uint32_t b_cofs = (q & 1) * 8;

    uint32_t stage = 0;   // rotating stage index (avoids %3)
    for (int s = 0; s < 64; s++) {
        if (s < 63) CP_WAIT(1); else CP_WAIT(0);
        __syncthreads();

        const uint32_t st = sb + stage * G_STAGE;

        uint32_t ah[2][4], al[2][4];
        #pragma unroll
        for (int mt = 0; mt < 2; mt++) {
            uint32_t ro = (wm + mt * 16 + a_row) * (GP2 * 2) + a_cofs * 2;
            ldsm_x4(st + ro,            ah[mt][0], ah[mt][1], ah[mt][2], ah[mt][3]);
            ldsm_x4(st + GA_BYTES + ro, al[mt][0], al[mt][1], al[mt][2], al[mt][3]);
        }
        // B in two halves to bound register liveness
        #pragma unroll
        for (int half = 0; half < 2; half++) {
            uint32_t bh[4][2], bl[4][2];
            #pragma unroll
            for (int np = 0; np < 2; np++) {
                uint32_t ro = (wn + (half * 2 + np) * 16 + b_row) * (GP2 * 2) + b_cofs * 2;
                ldsm_x4(st + 2 * GA_BYTES + ro,
                        bh[np*2][0], bh[np*2][1], bh[np*2+1][0], bh[np*2+1][1]);
                ldsm_x4(st + 2 * GA_BYTES + GB_BYTES + ro,
                        bl[np*2][0], bl[np*2][1], bl[np*2+1][0], bl[np*2+1][1]);
            }
            #pragma unroll
            for (int mt = 0; mt < 2; mt++)
                #pragma unroll
                for (int j = 0; j < 4; j++) {
                    int nt = half * 4 + j;
                    mma_bf16(acc[mt][nt], ah[mt], bh[j]);
                    mma_bf16(acc[mt][nt], ah[mt], bl[j]);
                    mma_bf16(acc[mt][nt], al[mt], bh[j]);
                }
        }

        if (s + 2 < 64) {
            uint32_t nstage = stage;          // (s+2)%3 == current stage slot freed 2 ago
            // stage for s+2 = (stage + 2) % 3
            nstage = (stage + 2 >= 3) ? (stage + 2 - 3) : (stage + 2);
            gemm_issue_stage(sb + nstage * G_STAGE, Ahi, Alo, Whi, Wlo,
                             m0, n0, (s + 2) * 16, tid);
            CP_COMMIT();
        }
        stage = (stage + 1 >= 3) ? 0 : (stage + 1);
    }

    // ---- epilogue
    const int g = lane >> 2, tq = lane & 3;
    const int which = (n0 >> 10);   // CTA-uniform (tile never crosses 1024)
    const float* bsel = (which == 0) ? bias0 : (which == 1) ? bias1 : bias2;

    #pragma unroll
    for (int mt = 0; mt < 2; mt++) {
        #pragma unroll
        for (int half = 0; half < 2; half++) {
            int m = m0 + wm + mt * 16 + g + half * 8;
            int b = m >> 11, t = m & 2047;
            #pragma unroll
            for (int nt = 0; nt < 8; nt++) {
                int n = n0 + wn + nt * 8 + 2 * tq;
                if (mode == 1) {
                    float2 v;
                    v.x = acc[mt][nt][half * 2 + 0] + __ldg(bias0 + n);
                    v.y = acc[mt][nt][half * 2 + 1] + __ldg(bias0 + n + 1);
                    *(float2*)(Cf + (size_t)m * 1024 + n) = v;
                } else {
                    int nn = n & 1023;
                    float vx = acc[mt][nt][half * 2 + 0] + __ldg(bsel + nn);
                    float vy = acc[mt][nt][half * 2 + 1] + __ldg(bsel + nn + 1);
                    int h = nn >> 6, d = nn & 63;
                    if (which == 2) {
                        // V transposed: [b,h,d,t]
                        size_t off = (((size_t)(b * 16 + h)) * 64 + d) * 2048 + t;
                        __nv_bfloat16 h0 = __float2bfloat16(vx);
                        __nv_bfloat16 h1 = __float2bfloat16(vy);
                        Vhi[off]        = h0;
                        Vhi[off + 2048] = h1;
                        Vlo[off]        = __float2bfloat16(vx - __bfloat162float(h0));
                        Vlo[off + 2048] = __float2bfloat16(vy - __bfloat162float(h1));
                    } else {
                        size_t off = (((size_t)(b * 16 + h)) * 2048 + t) * 64 + d;
                        uint32_t hi, lo;
                        split2(vx, vy, hi, lo);
                        if (which == 0) {
                            *(uint32_t*)(Qhi + off) = hi;
                            *(uint32_t*)(Qlo + off) = lo;
                        } else {
                            *(uint32_t*)(Khi + off) = hi;
                            *(uint32_t*)(Klo + off) = lo;
                        }
                    }
                }
            }
        }
    }
}

// ---------------- tensor-core flash attention (causal) -----------------------
#define AP 72                              // smem pitch in bf16 (144B rows)
#define ATILE (64 * AP * 2)                // 9216 B per 64x64 tile
#define AQ_OFF 0
#define AST_OFF (2 * ATILE)
#define ASTAGE (4 * ATILE)
#define ATTN_SMEM (AST_OFF + 2 * ASTAGE)   // 92160

__device__ __forceinline__ void attn_load_tile(uint32_t sbase,
    const __nv_bfloat16* __restrict__ gsrc, int rowstride, int tid)
{
    #pragma unroll
    for (int it = 0; it < 4; it++) {
        int idx = it * 128 + tid;          // 0..511
        int r = idx >> 3, c = idx & 7;
        cp_async16(sbase + r * (AP * 2) + c * 16,
                   gsrc + (size_t)r * rowstride + c * 8);
    }
}

__global__ __launch_bounds__(128) void attn_tc_kernel(
    const __nv_bfloat16* __restrict__ Qhi, const __nv_bfloat16* __restrict__ Qlo,
    const __nv_bfloat16* __restrict__ Khi, const __nv_bfloat16* __restrict__ Klo,
    const __nv_bfloat16* __restrict__ VThi, const __nv_bfloat16* __restrict__ VTlo,
    __nv_bfloat16* __restrict__ Ahi, __nv_bfloat16* __restrict__ Alo)
{
    extern __shared__ char smem[];
    const uint32_t sb = smem_u32(smem);
    const int tid = threadIdx.x;
    const int w = tid >> 5, lane = tid & 31;
    const int qi = blockIdx.x, bh = blockIdx.y;
    const size_t baseTD = (size_t)bh * T_ * 64;
    const int rl = lane & 7, q = lane >> 3;
    const int g = lane >> 2, tq = lane & 3;

    attn_load_tile(sb + AQ_OFF,         Qhi + baseTD + (size_t)qi * 64 * 64, 64, tid);
    attn_load_tile(sb + AQ_OFF + ATILE, Qlo + baseTD + (size_t)qi * 64 * 64, 64, tid);
    CP_COMMIT();
    {
        uint32_t st0 = sb + AST_OFF;
        attn_load_tile(st0 + 0*ATILE, Khi + baseTD, 64, tid);
        attn_load_tile(st0 + 1*ATILE, Klo + baseTD, 64, tid);
        attn_load_tile(st0 + 2*ATILE, VThi + baseTD, 2048, tid);
        attn_load_tile(st0 + 3*ATILE, VTlo + baseTD, 2048, tid);
        CP_COMMIT();
    }

    CP_WAIT(1);
    __syncthreads();

    const uint32_t a_row = rl + (q & 1) * 8, a_cofs = (q >> 1) * 8;
    const uint32_t b_row = rl + (q >> 1) * 8, b_cofs = (q & 1) * 8;
    uint32_t qh[4][4], ql[4][4];
    #pragma unroll
    for (int kk = 0; kk < 4; kk++) {
        uint32_t ro = (w * 16 + a_row) * (AP * 2) + (kk * 16 + a_cofs) * 2;
        ldsm_x4(sb + AQ_OFF + ro,         qh[kk][0], qh[kk][1], qh[kk][2], qh[kk][3]);
        ldsm_x4(sb + AQ_OFF + ATILE + ro, ql[kk][0], ql[kk][1], ql[kk][2], ql[kk][3]);
    }

    float oacc[8][4];
    #pragma unroll
    for (int nt = 0; nt < 8; nt++)
        #pragma unroll
        for (int e = 0; e < 4; e++) oacc[nt][e] = 0.f;
    float m_r[2] = {-1e30f, -1e30f}, l_r[2] = {0.f, 0.f};

    for (int kt = 0; kt <= qi; kt++) {
        const uint32_t st = sb + AST_OFF + (kt & 1) * ASTAGE;
        if (kt < qi) {
            uint32_t ns = sb + AST_OFF + ((kt + 1) & 1) * ASTAGE;
            const size_t offT = baseTD + (size_t)(kt + 1) * 64 * 64;
            const size_t offV = baseTD + (size_t)(kt + 1) * 64;
            attn_load_tile(ns + 0*ATILE, Khi + offT, 64, tid);
            attn_load_tile(ns + 1*ATILE, Klo + offT, 64, tid);
            attn_load_tile(ns + 2*ATILE, VThi + offV, 2048, tid);
            attn_load_tile(ns + 3*ATILE, VTlo + offV, 2048, tid);
            CP_COMMIT();
            CP_WAIT(1);
        } else {
            CP_WAIT(0);
        }
        __syncthreads();

        float sacc[8][4];
        #pragma unroll
        for (int nt = 0; nt < 8; nt++)
            #pragma unroll
            for (int e = 0; e < 4; e++) sacc[nt][e] = 0.f;

        #pragma unroll
        for (int kk = 0; kk < 4; kk++) {
            uint32_t kh[8][2], kl[8][2];
            #pragma unroll
            for (int np = 0; np < 4; np++) {
                uint32_t ro = (np * 16 + b_row) * (AP * 2) + (kk * 16 + b_cofs) * 2;
                ldsm_x4(st + 0*ATILE + ro,
                        kh[np*2][0], kh[np*2][1], kh[np*2+1][0], kh[np*2+1][1]);
                ldsm_x4(st + 1*ATILE + ro,
                        kl[np*2][0], kl[np*2][1], kl[np*2+1][0], kl[np*2+1][1]);
            }
            #pragma unroll
            for (int nt = 0; nt < 8; nt++) {
                mma_bf16(sacc[nt], qh[kk], kh[nt]);
                mma_bf16(sacc[nt], qh[kk], kl[nt]);
                mma_bf16(sacc[nt], ql[kk], kh[nt]);
            }
        }

        const bool diag = (kt == qi);
        #pragma unroll
        for (int nt = 0; nt < 8; nt++) {
            #pragma unroll
            for (int e = 0; e < 4; e++) {
                float s = sacc[nt][e] * 0.125f;
                if (diag) {
                    int row = w * 16 + g + (e >> 1) * 8;
                    int col = nt * 8 + 2 * tq + (e & 1);
                    if (col > row) s = -1e30f;
                }
                sacc[nt][e] = s;
            }
        }

        #pragma unroll
        for (int r = 0; r < 2; r++) {
            float mloc = -1e30f;
            #pragma unroll
            for (int nt = 0; nt < 8; nt++)
                mloc = fmaxf(mloc, fmaxf(sacc[nt][r*2], sacc[nt][r*2+1]));
            mloc = fmaxf(mloc, __shfl_xor_sync(0xffffffffu, mloc, 1));
            mloc = fmaxf(mloc, __shfl_xor_sync(0xffffffffu, mloc, 2));
            float mnew = fmaxf(m_r[r], mloc);
            float rs = 0.f;
            #pragma unroll
            for (int nt = 0; nt < 8; nt++) {
                float p0 = __expf(sacc[nt][r*2]   - mnew);
                float p1 = __expf(sacc[nt][r*2+1] - mnew);
                sacc[nt][r*2] = p0; sacc[nt][r*2+1] = p1;
                rs += p0 + p1;
            }
            rs += __shfl_xor_sync(0xffffffffu, rs, 1);
            rs += __shfl_xor_sync(0xffffffffu, rs, 2);
            float corr = __expf(m_r[r] - mnew);
            l_r[r] = l_r[r] * corr + rs;
            m_r[r] = mnew;
            #pragma unroll
            for (int nt = 0; nt < 8; nt++) {
                oacc[nt][r*2]   *= corr;
                oacc[nt][r*2+1] *= corr;
            }
        }

        #pragma unroll
        for (int j = 0; j < 4; j++) {
            uint32_t pah[4], pal[4];
            split2(sacc[2*j][0],   sacc[2*j][1],   pah[0], pal[0]);
            split2(sacc[2*j][2],   sacc[2*j][3],   pah[1], pal[1]);
            split2(sacc[2*j+1][0], sacc[2*j+1][1], pah[2], pal[2]);
            split2(sacc[2*j+1][2], sacc[2*j+1][3], pah[3], pal[3]);

            uint32_t vh[8][2], vl[8][2];
            #pragma unroll
            for (int np = 0; np < 4; np++) {
                uint32_t ro = (np * 16 + b_row) * (AP * 2) + (j * 16 + b_cofs) * 2;
                ldsm_x4(st + 2*ATILE + ro,
                        vh[np*2][0], vh[np*2][1], vh[np*2+1][0], vh[np*2+1][1]);
                ldsm_x4(st + 3*ATILE + ro,
                        vl[np*2][0], vl[np*2][1], vl[np*2+1][0], vl[np*2+1][1]);
            }
            #pragma unroll
            for (int nt = 0; nt < 8; nt++) {
                mma_bf16(oacc[nt], pah, vh[nt]);
                mma_bf16(oacc[nt], pah, vl[nt]);
                mma_bf16(oacc[nt], pal, vh[nt]);
            }
        }
        __syncthreads();
    }

    const int b = bh >> 4, h = bh & 15;
    #pragma unroll
    for (int r = 0; r < 2; r++) {
        float inv = 1.0f / l_r[r];
        int t = qi * 64 + w * 16 + g + r * 8;
        size_t rowo = ((size_t)(b * T_ + t)) * DM_ + h * 64;
        #pragma unroll
        for (int nt = 0; nt < 8; nt++) {
            int d = nt * 8 + 2 * tq;
            uint32_t hi, lo;
            split2(oacc[nt][r*2] * inv, oacc[nt][r*2+1] * inv, hi, lo);
            *(uint32_t*)(Ahi + rowo + d) = hi;
            *(uint32_t*)(Alo + rowo + d) = lo;
        }
    }
}

// ---------------------------------------------------------------------------
extern "C" void kernel_launch(void* const* d_in, const int* in_sizes, int n_in,
                              void* d_out, int out_size)
{
    const float* x   = (const float*)d_in[0];
    const float* Wq  = (const float*)d_in[2];
    const float* Wqb = (const float*)d_in[3];
    const float* Wk  = (const float*)d_in[4];
    const float* Wkb = (const float*)d_in[5];
    const float* Wv  = (const float*)d_in[6];
    const float* Wvb = (const float*)d_in[7];
    const float* Wo  = (const float*)d_in[8];
    const float* Wob = (const float*)d_in[9];
    float* out = (float*)d_out;

    __nv_bfloat16 *xhi, *xlo, *whi, *wlo;
    __nv_bfloat16 *qhi, *qlo, *khi, *klo, *vhi, *vlo, *ahi, *alo;
    cudaGetSymbolAddress((void**)&xhi, g_xhi);
    cudaGetSymbolAddress((void**)&xlo, g_xlo);
    cudaGetSymbolAddress((void**)&whi, g_whi);
    cudaGetSymbolAddress((void**)&wlo, g_wlo);
    cudaGetSymbolAddress((void**)&qhi, g_qhi);
    cudaGetSymbolAddress((void**)&qlo, g_qlo);
    cudaGetSymbolAddress((void**)&khi, g_khi);
    cudaGetSymbolAddress((void**)&klo, g_klo);
    cudaGetSymbolAddress((void**)&vhi, g_vhi);
    cudaGetSymbolAddress((void**)&vlo, g_vlo);
    cudaGetSymbolAddress((void**)&ahi, g_ahi);
    cudaGetSymbolAddress((void**)&alo, g_alo);

    cudaFuncSetAttribute(gemm_tc_kernel, cudaFuncAttributeMaxDynamicSharedMemorySize, G_SMEM);
    cudaFuncSetAttribute(attn_tc_kernel, cudaFuncAttributeMaxDynamicSharedMemorySize, ATTN_SMEM);

    const int nx4 = M_ * DM_ / 4, nw4 = DM_ * DM_ / 4;
    split_bf16_kernel<<<nx4 / 256, 256>>>(x, xhi, xlo, nx4);
    split_bf16_kernel<<<nw4 / 256, 256>>>(Wq, whi + 0 * DM_ * DM_, wlo + 0 * DM_ * DM_, nw4);
    split_bf16_kernel<<<nw4 / 256, 256>>>(Wk, whi + 1 * DM_ * DM_, wlo + 1 * DM_ * DM_, nw4);
    split_bf16_kernel<<<nw4 / 256, 256>>>(Wv, whi + 2 * DM_ * DM_, wlo + 2 * DM_ * DM_, nw4);
    split_bf16_kernel<<<nw4 / 256, 256>>>(Wo, whi + 3 * DM_ * DM_, wlo + 3 * DM_ * DM_, nw4);

    // Fused QKV: N = 3072 (Wq|Wk|Wv rows are contiguous in g_whi)
    gemm_tc_kernel<<<dim3(3 * DM_ / 128, M_ / 64), 128, G_SMEM>>>(
        xhi, xlo, whi, wlo, Wqb, Wkb, Wvb,
        qhi, qlo, khi, klo, vhi, vlo, nullptr, 0);

    attn_tc_kernel<<<dim3(T_ / 64, B_ * H_), 128, ATTN_SMEM>>>(
        qhi, qlo, khi, klo, vhi, vlo, ahi, alo);

    // O-projection: fp32 out
    gemm_tc_kernel<<<dim3(DM_ / 128, M_ / 64), 128, G_SMEM>>>(
        ahi, alo, whi + 3 * DM_ * DM_, wlo + 3 * DM_ * DM_, Wob, nullptr, nullptr,
        nullptr, nullptr, nullptr, nullptr, nullptr, nullptr, out, 1);
}

// round 10
// speedup vs baseline: 2.7769x; 2.7769x over previous
#include <cuda_runtime.h>
#include <cuda_fp16.h>
#include <cstdint>

#define B_  4
#define H_  16
#define T_  2048
#define DK_ 64
#define DM_ 1024
#define M_  (B_*T_)     // 8192

// ---------------- scratch (device globals; no allocations allowed) ----------
__device__ __half g_xh[M_*DM_];
__device__ __half g_wh[4*DM_*DM_];   // Wq | Wk | Wv | Wo (contiguous)
__device__ __half g_qh[M_*DM_];      // [b,h,t,d]
__device__ __half g_kh[M_*DM_];      // [b,h,t,d]
__device__ __half g_vh[M_*DM_];      // [b,h,d,t]  (transposed!)
__device__ __half g_ah[M_*DM_];      // [b,t, h*64+d]

// ---------------- portable PTX helpers (family-safe) -------------------------
__device__ __forceinline__ uint32_t smem_u32(const void* p) {
    uint32_t a;
    asm("{ .reg .u64 t; cvta.to.shared.u64 t, %1; cvt.u32.u64 %0, t; }" : "=r"(a) : "l"(p));
    return a;
}
__device__ __forceinline__ void cp_async16(uint32_t saddr, const void* gaddr) {
    asm volatile("cp.async.cg.shared.global [%0], [%1], 16;" :: "r"(saddr), "l"(gaddr));
}
#define CP_COMMIT() asm volatile("cp.async.commit_group;" ::: "memory")
#define CP_WAIT(n)  asm volatile("cp.async.wait_group %0;" :: "n"(n) : "memory")

__device__ __forceinline__ void ldsm_x4(uint32_t addr, uint32_t& r0, uint32_t& r1,
                                        uint32_t& r2, uint32_t& r3) {
    asm volatile("ldmatrix.sync.aligned.m8n8.x4.shared.b16 {%0,%1,%2,%3}, [%4];"
                 : "=r"(r0), "=r"(r1), "=r"(r2), "=r"(r3) : "r"(addr));
}
__device__ __forceinline__ void mma_f16(float* c, const uint32_t* a, const uint32_t* b) {
    asm volatile(
        "mma.sync.aligned.m16n8k16.row.col.f32.f16.f16.f32 "
        "{%0,%1,%2,%3}, {%4,%5,%6,%7}, {%8,%9}, {%0,%1,%2,%3};"
        : "+f"(c[0]), "+f"(c[1]), "+f"(c[2]), "+f"(c[3])
        : "r"(a[0]), "r"(a[1]), "r"(a[2]), "r"(a[3]), "r"(b[0]), "r"(b[1]));
}
__device__ __forceinline__ uint32_t pack_half2(float a, float b) {
    __half2 h = __floats2half2_rn(a, b);
    return *(uint32_t*)&h;
}

// ---------------- fp32 -> fp16 convert ---------------------------------------
__global__ __launch_bounds__(256) void tohalf_kernel(
    const float* __restrict__ x, __half* __restrict__ y, int n4)
{
    int i = blockIdx.x * blockDim.x + threadIdx.x;
    if (i >= n4) return;
    float4 v = ((const float4*)x)[i];
    uint2 o;
    o.x = pack_half2(v.x, v.y);
    o.y = pack_half2(v.z, v.w);
    ((uint2*)y)[i] = o;
}

// ---------------- mma.sync fp16 GEMM -----------------------------------------
// CTA 128(m) x 128(n), BK=32, 4-stage cp.async, 256 thr = 8 warps 4(m)x2(n),
// warp tile 32x64. mode 0: fused QKV epilogue (N=3072, n>>10 selects Q/K/V);
// mode 1: fp32 row-major out (+bias).
#define GPH 40                              // smem pitch (fp16): 80B rows
#define GT_BYTES (128 * GPH * 2)            // 10240 B per 128x32 tile
#define G_STAGE (2 * GT_BYTES)              // 20480 B (A, B)
#define G_SMEM (4 * G_STAGE)                // 81920 B -> 2 CTAs/SM

__device__ __forceinline__ void gemm_issue_stage(uint32_t base,
    const __half* __restrict__ Ah, const __half* __restrict__ Wh,
    int m0, int n0, int k0, int tid)
{
    // each tile: 128 rows x 64B (4 x 16B chunks) = 512 chunks / 256 thr = 2 iters
    #pragma unroll
    for (int it = 0; it < 2; it++) {
        int idx = it * 256 + tid;
        int r = idx >> 2, c = idx & 3;
        const uint32_t so = r * (GPH * 2) + c * 16;
        cp_async16(base + so,            Ah + (size_t)(m0 + r) * 1024 + k0 + c * 8);
        cp_async16(base + GT_BYTES + so, Wh + (size_t)(n0 + r) * 1024 + k0 + c * 8);
    }
}

__global__ __launch_bounds__(256, 2) void gemm_tc_kernel(
    const __half* __restrict__ Ah, const __half* __restrict__ Wh,
    const float* __restrict__ bias0, const float* __restrict__ bias1,
    const float* __restrict__ bias2,
    __half* __restrict__ Qh, __half* __restrict__ Kh, __half* __restrict__ Vh,
    float* __restrict__ Cf, int mode)
{
    extern __shared__ char smem[];
    const uint32_t sb = smem_u32(smem);
    const int tid = threadIdx.x;
    const int wid = tid >> 5, lane = tid & 31;
    const int m0 = blockIdx.y * 128, n0 = blockIdx.x * 128;
    const int wm = (wid & 3) * 32;        // warp m-offset
    const int wn = (wid >> 2) * 64;       // warp n-offset
    const int rl = lane & 7, q = lane >> 3;

    float acc[2][8][4];
    #pragma unroll
    for (int mt = 0; mt < 2; mt++)
        #pragma unroll
        for (int nt = 0; nt < 8; nt++)
            #pragma unroll
            for (int e = 0; e < 4; e++) acc[mt][nt][e] = 0.f;

    // prologue: stages 0..2 in flight
    #pragma unroll
    for (int p = 0; p < 3; p++) {
        gemm_issue_stage(sb + p * G_STAGE, Ah, Wh, m0, n0, p * 32, tid);
        CP_COMMIT();
    }

    const uint32_t a_row = rl + (q & 1) * 8;
    const uint32_t a_cofs = (q >> 1) * 8;
    const uint32_t b_row = rl + (q >> 1) * 8;
    const uint32_t b_cofs = (q & 1) * 8;

    for (int s = 0; s < 32; s++) {
        if (s <= 29)      CP_WAIT(2);
        else if (s == 30) CP_WAIT(1);
        else              CP_WAIT(0);
        __syncthreads();

        const uint32_t st = sb + (s & 3) * G_STAGE;

        #pragma unroll
        for (int kk = 0; kk < 2; kk++) {
            uint32_t af[2][4];
            #pragma unroll
            for (int mt = 0; mt < 2; mt++) {
                uint32_t ro = (wm + mt * 16 + a_row) * (GPH * 2) + (kk * 16 + a_cofs) * 2;
                ldsm_x4(st + ro, af[mt][0], af[mt][1], af[mt][2], af[mt][3]);
            }
            uint32_t bf[8][2];
            #pragma unroll
            for (int np = 0; np < 4; np++) {
                uint32_t ro = (wn + np * 16 + b_row) * (GPH * 2) + (kk * 16 + b_cofs) * 2;
                ldsm_x4(st + GT_BYTES + ro,
                        bf[np*2][0], bf[np*2][1], bf[np*2+1][0], bf[np*2+1][1]);
            }
            #pragma unroll
            for (int mt = 0; mt < 2; mt++)
                #pragma unroll
                for (int nt = 0; nt < 8; nt++)
                    mma_f16(acc[mt][nt], af[mt], bf[nt]);
        }

        if (s + 3 < 32) {
            gemm_issue_stage(sb + ((s + 3) & 3) * G_STAGE, Ah, Wh,
                             m0, n0, (s + 3) * 32, tid);
            CP_COMMIT();
        }
    }

    // ---- epilogue
    const int g = lane >> 2, tq = lane & 3;
    const int which = (n0 >> 10);   // CTA-uniform (tile never crosses 1024)
    const float* bsel = (which == 0) ? bias0 : (which == 1) ? bias1 : bias2;

    #pragma unroll
    for (int mt = 0; mt < 2; mt++) {
        #pragma unroll
        for (int half = 0; half < 2; half++) {
            int m = m0 + wm + mt * 16 + g + half * 8;
            int b = m >> 11, t = m & 2047;
            #pragma unroll
            for (int nt = 0; nt < 8; nt++) {
                int n = n0 + wn + nt * 8 + 2 * tq;
                if (mode == 1) {
                    float2 v;
                    v.x = acc[mt][nt][half * 2 + 0] + __ldg(bias0 + n);
                    v.y = acc[mt][nt][half * 2 + 1] + __ldg(bias0 + n + 1);
                    *(float2*)(Cf + (size_t)m * 1024 + n) = v;
                } else {
                    int nn = n & 1023;
                    float vx = acc[mt][nt][half * 2 + 0] + __ldg(bsel + nn);
                    float vy = acc[mt][nt][half * 2 + 1] + __ldg(bsel + nn + 1);
                    int h = nn >> 6, d = nn & 63;
                    if (which == 2) {
                        // V transposed: [b,h,d,t]
                        size_t off = (((size_t)(b * 16 + h)) * 64 + d) * 2048 + t;
                        Vh[off]        = __float2half_rn(vx);
                        Vh[off + 2048] = __float2half_rn(vy);
                    } else {
                        size_t off = (((size_t)(b * 16 + h)) * 2048 + t) * 64 + d;
                        uint32_t pv = pack_half2(vx, vy);
                        if (which == 0) *(uint32_t*)(Qh + off) = pv;
                        else            *(uint32_t*)(Kh + off) = pv;
                    }
                }
            }
        }
    }
}

// ---------------- tensor-core flash attention (fp16, causal) -----------------
// grid (T/64, B*H), 128 thr = 4 warps; warp w owns Q rows w*16..w*16+15.
#define AP 72                              // smem pitch in fp16 (144B rows)
#define ATILE (64 * AP * 2)                // 9216 B per 64x64 tile
#define AST_OFF ATILE                      // stages after Q tile
#define ASTAGE (2 * ATILE)                 // K, V
#define ATTN_SMEM (ATILE + 2 * ASTAGE)     // 46080 B

__device__ __forceinline__ void attn_load_tile(uint32_t sbase,
    const __half* __restrict__ gsrc, int rowstride, int tid)
{
    #pragma unroll
    for (int it = 0; it < 4; it++) {
        int idx = it * 128 + tid;          // 0..511
        int r = idx >> 3, c = idx & 7;
        cp_async16(sbase + r * (AP * 2) + c * 16,
                   gsrc + (size_t)r * rowstride + c * 8);
    }
}

__global__ __launch_bounds__(128, 3) void attn_tc_kernel(
    const __half* __restrict__ Qh, const __half* __restrict__ Kh,
    const __half* __restrict__ VTh, __half* __restrict__ Ah)
{
    extern __shared__ char smem[];
    const uint32_t sb = smem_u32(smem);
    const int tid = threadIdx.x;
    const int w = tid >> 5, lane = tid & 31;
    const int qi = blockIdx.x, bh = blockIdx.y;
    const size_t baseTD = (size_t)bh * T_ * 64;
    const int rl = lane & 7, q = lane >> 3;
    const int g = lane >> 2, tq = lane & 3;

    attn_load_tile(sb, Qh + baseTD + (size_t)qi * 64 * 64, 64, tid);
    CP_COMMIT();
    {
        uint32_t st0 = sb + AST_OFF;
        attn_load_tile(st0,         Kh + baseTD, 64, tid);
        attn_load_tile(st0 + ATILE, VTh + baseTD, 2048, tid);
        CP_COMMIT();
    }

    CP_WAIT(1);
    __syncthreads();

    const uint32_t a_row = rl + (q & 1) * 8, a_cofs = (q >> 1) * 8;
    const uint32_t b_row = rl + (q >> 1) * 8, b_cofs = (q & 1) * 8;
    uint32_t qf[4][4];
    #pragma unroll
    for (int kk = 0; kk < 4; kk++) {
        uint32_t ro = (w * 16 + a_row) * (AP * 2) + (kk * 16 + a_cofs) * 2;
        ldsm_x4(sb + ro, qf[kk][0], qf[kk][1], qf[kk][2], qf[kk][3]);
    }

    float oacc[8][4];
    #pragma unroll
    for (int nt = 0; nt < 8; nt++)
        #pragma unroll
        for (int e = 0; e < 4; e++) oacc[nt][e] = 0.f;
    float m_r[2] = {-1e30f, -1e30f}, l_r[2] = {0.f, 0.f};

    for (int kt = 0; kt <= qi; kt++) {
        const uint32_t st = sb + AST_OFF + (kt & 1) * ASTAGE;
        if (kt < qi) {
            uint32_t ns = sb + AST_OFF + ((kt + 1) & 1) * ASTAGE;
            attn_load_tile(ns,         Kh + baseTD + (size_t)(kt + 1) * 64 * 64, 64, tid);
            attn_load_tile(ns + ATILE, VTh + baseTD + (size_t)(kt + 1) * 64, 2048, tid);
            CP_COMMIT();
            CP_WAIT(1);
        } else {
            CP_WAIT(0);
        }
        __syncthreads();

        // ---- S = Q K^T
        float sacc[8][4];
        #pragma unroll
        for (int nt = 0; nt < 8; nt++)
            #pragma unroll
            for (int e = 0; e < 4; e++) sacc[nt][e] = 0.f;

        #pragma unroll
        for (int kk = 0; kk < 4; kk++) {
            uint32_t kf[8][2];
            #pragma unroll
            for (int np = 0; np < 4; np++) {
                uint32_t ro = (np * 16 + b_row) * (AP * 2) + (kk * 16 + b_cofs) * 2;
                ldsm_x4(st + ro,
                        kf[np*2][0], kf[np*2][1], kf[np*2+1][0], kf[np*2+1][1]);
            }
            #pragma unroll
            for (int nt = 0; nt < 8; nt++)
                mma_f16(sacc[nt], qf[kk], kf[nt]);
        }

        // ---- scale + causal mask
        const bool diag = (kt == qi);
        #pragma unroll
        for (int nt = 0; nt < 8; nt++) {
            #pragma unroll
            for (int e = 0; e < 4; e++) {
                float s = sacc[nt][e] * 0.125f;
                if (diag) {
                    int row = w * 16 + g + (e >> 1) * 8;
                    int col = nt * 8 + 2 * tq + (e & 1);
                    if (col > row) s = -1e30f;
                }
                sacc[nt][e] = s;
            }
        }

        // ---- online softmax (per thread: rows g, g+8)
        #pragma unroll
        for (int r = 0; r < 2; r++) {
            float mloc = -1e30f;
            #pragma unroll
            for (int nt = 0; nt < 8; nt++)
                mloc = fmaxf(mloc, fmaxf(sacc[nt][r*2], sacc[nt][r*2+1]));
            mloc = fmaxf(mloc, __shfl_xor_sync(0xffffffffu, mloc, 1));
            mloc = fmaxf(mloc, __shfl_xor_sync(0xffffffffu, mloc, 2));
            float mnew = fmaxf(m_r[r], mloc);
            float rs = 0.f;
            #pragma unroll
            for (int nt = 0; nt < 8; nt++) {
                float p0 = __expf(sacc[nt][r*2]   - mnew);
                float p1 = __expf(sacc[nt][r*2+1] - mnew);
                sacc[nt][r*2] = p0; sacc[nt][r*2+1] = p1;
                rs += p0 + p1;
            }
            rs += __shfl_xor_sync(0xffffffffu, rs, 1);
            rs += __shfl_xor_sync(0xffffffffu, rs, 2);
            float corr = __expf(m_r[r] - mnew);
            l_r[r] = l_r[r] * corr + rs;
            m_r[r] = mnew;
            #pragma unroll
            for (int nt = 0; nt < 8; nt++) {
                oacc[nt][r*2]   *= corr;
                oacc[nt][r*2+1] *= corr;
            }
        }

        // ---- O += P V
        #pragma unroll
        for (int j = 0; j < 4; j++) {
            uint32_t pf[4];
            pf[0] = pack_half2(sacc[2*j][0],   sacc[2*j][1]);
            pf[1] = pack_half2(sacc[2*j][2],   sacc[2*j][3]);
            pf[2] = pack_half2(sacc[2*j+1][0], sacc[2*j+1][1]);
            pf[3] = pack_half2(sacc[2*j+1][2], sacc[2*j+1][3]);

            uint32_t vf[8][2];
            #pragma unroll
            for (int np = 0; np < 4; np++) {
                uint32_t ro = (np * 16 + b_row) * (AP * 2) + (j * 16 + b_cofs) * 2;
                ldsm_x4(st + ATILE + ro,
                        vf[np*2][0], vf[np*2][1], vf[np*2+1][0], vf[np*2+1][1]);
            }
            #pragma unroll
            for (int nt = 0; nt < 8; nt++)
                mma_f16(oacc[nt], pf, vf[nt]);
        }
        __syncthreads();
    }

    // ---- epilogue: normalize, write fp16 [b,t,h*64+d]
    const int b = bh >> 4, h = bh & 15;
    #pragma unroll
    for (int r = 0; r < 2; r++) {
        float inv = 1.0f / l_r[r];
        int t = qi * 64 + w * 16 + g + r * 8;
        size_t rowo = ((size_t)(b * T_ + t)) * DM_ + h * 64;
        #pragma unroll
        for (int nt = 0; nt < 8; nt++) {
            int d = nt * 8 + 2 * tq;
            *(uint32_t*)(Ah + rowo + d) =
                pack_half2(oacc[nt][r*2] * inv, oacc[nt][r*2+1] * inv);
        }
    }
}

// ---------------------------------------------------------------------------
extern "C" void kernel_launch(void* const* d_in, const int* in_sizes, int n_in,
                              void* d_out, int out_size)
{
    const float* x   = (const float*)d_in[0];
    const float* Wq  = (const float*)d_in[2];
    const float* Wqb = (const float*)d_in[3];
    const float* Wk  = (const float*)d_in[4];
    const float* Wkb = (const float*)d_in[5];
    const float* Wv  = (const float*)d_in[6];
    const float* Wvb = (const float*)d_in[7];
    const float* Wo  = (const float*)d_in[8];
    const float* Wob = (const float*)d_in[9];
    float* out = (float*)d_out;

    __half *xh, *wh, *qh, *kh, *vh, *ah;
    cudaGetSymbolAddress((void**)&xh, g_xh);
    cudaGetSymbolAddress((void**)&wh, g_wh);
    cudaGetSymbolAddress((void**)&qh, g_qh);
    cudaGetSymbolAddress((void**)&kh, g_kh);
    cudaGetSymbolAddress((void**)&vh, g_vh);
    cudaGetSymbolAddress((void**)&ah, g_ah);

    cudaFuncSetAttribute(gemm_tc_kernel, cudaFuncAttributeMaxDynamicSharedMemorySize, G_SMEM);
    cudaFuncSetAttribute(attn_tc_kernel, cudaFuncAttributeMaxDynamicSharedMemorySize, ATTN_SMEM);

    const int nx4 = M_ * DM_ / 4, nw4 = DM_ * DM_ / 4;
    tohalf_kernel<<<nx4 / 256, 256>>>(x, xh, nx4);
    tohalf_kernel<<<nw4 / 256, 256>>>(Wq, wh + 0 * DM_ * DM_, nw4);
    tohalf_kernel<<<nw4 / 256, 256>>>(Wk, wh + 1 * DM_ * DM_, nw4);
    tohalf_kernel<<<nw4 / 256, 256>>>(Wv, wh + 2 * DM_ * DM_, nw4);
    tohalf_kernel<<<nw4 / 256, 256>>>(Wo, wh + 3 * DM_ * DM_, nw4);

    // Fused QKV: N = 3072 (Wq|Wk|Wv rows contiguous in g_wh)
    gemm_tc_kernel<<<dim3(3 * DM_ / 128, M_ / 128), 256, G_SMEM>>>(
        xh, wh, Wqb, Wkb, Wvb, qh, kh, vh, nullptr, 0);

    attn_tc_kernel<<<dim3(T_ / 64, B_ * H_), 128, ATTN_SMEM>>>(qh, kh, vh, ah);

    // O-projection: fp32 out
    gemm_tc_kernel<<<dim3(DM_ / 128, M_ / 128), 256, G_SMEM>>>(
        ah, wh + 3 * DM_ * DM_, Wob, nullptr, nullptr,
        nullptr, nullptr, nullptr, out, 1);
}